// round 14
// baseline (speedup 1.0000x reference)
#include <cuda_runtime.h>
#include <math.h>

#define MAXN 10000
#define MAXE 160000
#define NB   64

typedef unsigned long long ull;
#define FMA2(d,a,b,c) asm("fma.rn.f32x2 %0, %1, %2, %3;" : "=l"(d) : "l"(a), "l"(b), "l"(c))
#define PACK2(d,x,y)  asm("mov.b64 %0, {%1, %2};" : "=l"(d) : "f"(x), "f"(y))

// ---------------- device scratch ----------------
__device__ float g_out[MAXN * 32];
__device__ float g_agg[MAXN * 32];
__device__ float g_deg[MAXN];
__device__ float g_W2x[32 * 4128];
__device__ float g_T  [MAXN * 4128];
__device__ int   g_cnt[MAXN];
__device__ int   g_off[MAXN];
__device__ int   g_pos[MAXN];
__device__ int   g_eid[MAXE];
__device__ float g_q   [NB * 32];
__device__ float g_hh  [NB * 32];
__device__ float g_cc  [NB * 32];
__device__ float g_sumexp[NB];
__device__ float g_rnum[NB * 32];

// ---------------- fused setup: init out/agg/deg/cnt + W2x transform ----------------
// grid MUST cover max(N*32, 32*4128) indices
__global__ void k_setup(const float* __restrict__ x, const float* __restrict__ w0,
                        const float* __restrict__ b0,
                        const float* __restrict__ w2, const float* __restrict__ b2,
                        int n_nodes) {
    int idx = blockIdx.x * blockDim.x + threadIdx.x;
    if (idx < n_nodes) { g_deg[idx] = 0.f; g_cnt[idx] = 0; }
    if (idx < n_nodes * 32) {
        int n = idx >> 5, o = idx & 31;
        float v = x[n] * w0[o] + b0[o];
        g_out[idx] = v > 0.f ? v : 0.f;
        g_agg[idx] = 0.f;
    }
    if (idx < 32 * 4128) {
        int i = idx / 4128, c = idx % 4128;
        float v;
        if (c < 4096) { int k = c >> 5, o = c & 31; v = w2[k * 1024 + i * 32 + o]; }
        else          { v = b2[i * 32 + (c - 4096)]; }
        g_W2x[idx] = v;
    }
}

__global__ void k_count(const int* __restrict__ ei, int n_edges) {
    int e = blockIdx.x * blockDim.x + threadIdx.x;
    if (e >= n_edges) return;
    atomicAdd(&g_deg[ei[n_edges + e]], 1.0f);
    atomicAdd(&g_cnt[ei[e]], 1);
}

__global__ void k_scan(int n_nodes) {
    __shared__ int wsum[32];
    int tid = threadIdx.x;  // 1024
    int lane = tid & 31, wid = tid >> 5;
    int CH = (n_nodes + 1023) >> 10;
    int base = tid * CH;
    int s = 0;
#pragma unroll 4
    for (int j = 0; j < CH; j++) { int i = base + j; if (i < n_nodes) s += g_cnt[i]; }
    int v = s;
#pragma unroll
    for (int off = 1; off < 32; off <<= 1) {
        int u = __shfl_up_sync(0xffffffffu, v, off);
        if (lane >= off) v += u;
    }
    if (lane == 31) wsum[wid] = v;
    __syncthreads();
    if (wid == 0) {
        int w = wsum[lane];
#pragma unroll
        for (int off = 1; off < 32; off <<= 1) {
            int u = __shfl_up_sync(0xffffffffu, w, off);
            if (lane >= off) w += u;
        }
        wsum[lane] = w;
    }
    __syncthreads();
    int run = v - s + (wid ? wsum[wid - 1] : 0);
    for (int j = 0; j < CH; j++) {
        int i = base + j;
        if (i < n_nodes) { g_off[i] = run; g_pos[i] = run; run += g_cnt[i]; }
    }
}

__global__ void k_scatter(const int* __restrict__ ei, int n_edges) {
    int e = blockIdx.x * blockDim.x + threadIdx.x;
    if (e >= n_edges) return;
    int p = atomicAdd(&g_pos[ei[e]], 1);
    g_eid[p] = e;
}

// ---------------- T' = out @ W2x : 2 cols x 16 nodes, depth-2 W2x prefetch ----------------
__global__ void __launch_bounds__(256, 4) k_T(int n0, int n1) {
    __shared__ float outT[32 * 20];
    int ct = blockIdx.x;              // 0..8, 512-col tiles
    int tid = threadIdx.x;            // 256
    int nb = n0 + blockIdx.y * 16;
    for (int idx = tid; idx < 512; idx += 256) {
        int node = idx >> 5, i = idx & 31;
        int n = nb + node;
        outT[i * 20 + node] = (n < n1) ? g_out[n * 32 + i] : 0.f;
    }
    __syncthreads();
    int colA = ct * 512 + tid;
    int colB = colA + 256;
    bool vA = colA < 4128, vB = colB < 4128;
    if (!vA) return;
    const float* wAp = &g_W2x[colA];
    const float* wBp = &g_W2x[colB];
    ull accA[8], accB[8];
#pragma unroll
    for (int j = 0; j < 8; j++) { accA[j] = 0ull; accB[j] = 0ull; }
    float wa0 = wAp[0];
    float wb0 = vB ? wBp[0] : 0.f;
    float wa1 = wAp[4128];
    float wb1 = vB ? wBp[4128] : 0.f;
#pragma unroll
    for (int i = 0; i < 32; i++) {
        ull wpa, wpb;
        PACK2(wpa, wa0, wa0);
        PACK2(wpb, wb0, wb0);
        wa0 = wa1; wb0 = wb1;
        if (i < 30) {
            wa1 = wAp[(i + 2) * 4128];
            wb1 = vB ? wBp[(i + 2) * 4128] : 0.f;
        }
        const longlong2* op = (const longlong2*)&outT[i * 20];
#pragma unroll
        for (int q = 0; q < 4; q++) {
            longlong2 v = op[q];
            FMA2(accA[2 * q + 0], (ull)v.x, wpa, accA[2 * q + 0]);
            FMA2(accA[2 * q + 1], (ull)v.y, wpa, accA[2 * q + 1]);
            FMA2(accB[2 * q + 0], (ull)v.x, wpb, accB[2 * q + 0]);
            FMA2(accB[2 * q + 1], (ull)v.y, wpb, accB[2 * q + 1]);
        }
    }
#pragma unroll
    for (int j = 0; j < 8; j++) {
        float2 fA = *(float2*)&accA[j];
        float2 fB = *(float2*)&accB[j];
        int nA = nb + 2 * j;
        if (nA < n1) {
            g_T[(size_t)nA * 4128 + colA] = fA.x;
            if (vB) g_T[(size_t)nA * 4128 + colB] = fB.x;
        }
        if (nA + 1 < n1) {
            g_T[(size_t)(nA + 1) * 4128 + colA] = fA.y;
            if (vB) g_T[(size_t)(nA + 1) * 4128 + colB] = fB.y;
        }
    }
}

// ---------------- edge messages: 4 warps/node, 4-edge chunks ----------------
__global__ void k_edge(const int* __restrict__ ei, const float* __restrict__ ea,
                       const float* __restrict__ nn_w1, const float* __restrict__ nn_b1,
                       int n_edges, int n0) {
    __shared__ float Ts[4128];
    __shared__ float h1s[4][4 * 132];
    __shared__ int   eidS[4][4];
    __shared__ int   dstS[4][4];
    __shared__ float eaS[4][4][2];
    int n = n0 + blockIdx.x;
    int cnt = g_cnt[n];
    if (cnt == 0) return;
    int start = g_off[n];
    int tid = threadIdx.x;  // 128
    int w = tid >> 5, lane = tid & 31;
    float4 w1a = *(const float4*)&nn_w1[lane * 4];
    float4 w1b = *(const float4*)&nn_w1[128 + lane * 4];
    float4 b1v = *(const float4*)&nn_b1[lane * 4];
    {
        const float4* Tg = (const float4*)&g_T[(size_t)n * 4128];
        float4* Ts4 = (float4*)Ts;
        for (int i = tid; i < 1032; i += 128) Ts4[i] = Tg[i];
    }
    __syncthreads();
    int og = lane & 7;       // output group (outputs 4og..4og+3)
    int eg = lane >> 3;      // edge within chunk (0..3)
    const float* hp = &h1s[w][eg * 132];
    int nch = (cnt + 3) >> 2;
    for (int c = w; c < nch; c += 4) {
        if (lane < 4) {
            int idx = c * 4 + lane;
            int e = (idx < cnt) ? g_eid[start + idx] : -1;
            eidS[w][lane] = e;
            dstS[w][lane] = (e >= 0) ? ei[n_edges + e] : 0;
            float2 e2 = (e >= 0) ? *(const float2*)&ea[2 * e] : make_float2(0.f, 0.f);
            eaS[w][lane][0] = e2.x; eaS[w][lane][1] = e2.y;
        }
        __syncwarp();
#pragma unroll
        for (int r = 0; r < 4; r++) {
            float a0 = eaS[w][r][0], a1 = eaS[w][r][1];
            float4 h;
            h.x = fmaxf(a0 * w1a.x + a1 * w1b.x + b1v.x, 0.f);
            h.y = fmaxf(a0 * w1a.y + a1 * w1b.y + b1v.y, 0.f);
            h.z = fmaxf(a0 * w1a.z + a1 * w1b.z + b1v.z, 0.f);
            h.w = fmaxf(a0 * w1a.w + a1 * w1b.w + b1v.w, 0.f);
            *(float4*)&h1s[w][r * 132 + lane * 4] = h;
        }
        __syncwarp();
        longlong2 bb = *(const longlong2*)&Ts[4096 + og * 4];
        ull a0 = (ull)bb.x, a1 = (ull)bb.y;
#pragma unroll 4
        for (int k = 0; k < 128; k += 4) {
            longlong2 t0 = *(const longlong2*)&Ts[(k + 0) * 32 + og * 4];
            longlong2 t1 = *(const longlong2*)&Ts[(k + 1) * 32 + og * 4];
            longlong2 t2 = *(const longlong2*)&Ts[(k + 2) * 32 + og * 4];
            longlong2 t3 = *(const longlong2*)&Ts[(k + 3) * 32 + og * 4];
            float4 h = *(const float4*)&hp[k];
            ull hh;
            PACK2(hh, h.x, h.x);
            FMA2(a0, hh, (ull)t0.x, a0); FMA2(a1, hh, (ull)t0.y, a1);
            PACK2(hh, h.y, h.y);
            FMA2(a0, hh, (ull)t1.x, a0); FMA2(a1, hh, (ull)t1.y, a1);
            PACK2(hh, h.z, h.z);
            FMA2(a0, hh, (ull)t2.x, a0); FMA2(a1, hh, (ull)t2.y, a1);
            PACK2(hh, h.w, h.w);
            FMA2(a0, hh, (ull)t3.x, a0); FMA2(a1, hh, (ull)t3.y, a1);
        }
        int e = eidS[w][eg];
        if (e >= 0) {
            float2 f0 = *(float2*)&a0, f1 = *(float2*)&a1;
            float* ap = &g_agg[(size_t)dstS[w][eg] * 32 + og * 4];
            atomicAdd(ap + 0, f0.x); atomicAdd(ap + 1, f0.y);
            atomicAdd(ap + 2, f1.x); atomicAdd(ap + 3, f1.y);
        }
        __syncwarp();
    }
}

// ---------------- GRU node update (re-zeroes agg) ----------------
__global__ void k_update(const float* __restrict__ conv_root, const float* __restrict__ conv_bias,
                         const float* __restrict__ w_ih, const float* __restrict__ w_hh,
                         const float* __restrict__ b_ih, const float* __restrict__ b_hh,
                         int n_nodes) {
    int warp = (blockIdx.x * blockDim.x + threadIdx.x) >> 5;
    int lane = threadIdx.x & 31;
    if (warp >= n_nodes) return;
    int n = warp;
    float hv = g_out[n * 32 + lane];
    float m = g_agg[n * 32 + lane] / fmaxf(g_deg[n], 1.f) + conv_bias[lane];
    g_agg[n * 32 + lane] = 0.f;
#pragma unroll
    for (int i = 0; i < 32; i++) {
        float oi = __shfl_sync(0xffffffffu, hv, i);
        m += oi * conv_root[i * 32 + lane];
    }
    m = fmaxf(m, 0.f);
    float gr = b_ih[lane], gz = b_ih[32 + lane], gn = b_ih[64 + lane];
    float hr = b_hh[lane], hz = b_hh[32 + lane], hn = b_hh[64 + lane];
#pragma unroll
    for (int i = 0; i < 32; i++) {
        float mi = __shfl_sync(0xffffffffu, m, i);
        float hi = __shfl_sync(0xffffffffu, hv, i);
        gr += mi * w_ih[i * 96 + lane];
        gz += mi * w_ih[i * 96 + 32 + lane];
        gn += mi * w_ih[i * 96 + 64 + lane];
        hr += hi * w_hh[i * 96 + lane];
        hz += hi * w_hh[i * 96 + 32 + lane];
        hn += hi * w_hh[i * 96 + 64 + lane];
    }
    float rg = 1.f / (1.f + expf(-(gr + hr)));
    float zg = 1.f / (1.f + expf(-(gz + hz)));
    float ng = tanhf(gn + rg * hn);
    g_out[n * 32 + lane] = (1.f - zg) * ng + zg * hv;
}

// ---------------- Set2Set LSTM step ----------------
__global__ void k_lstm(const float* __restrict__ w_ih, const float* __restrict__ w_hh,
                       const float* __restrict__ b_ih, const float* __restrict__ b_hh, int t) {
    __shared__ float qsS[8 * 64];
    __shared__ float hhS[8 * 32];
    __shared__ float ccS[8 * 32];
    int tid = threadIdx.x;  // 256
    int b0 = blockIdx.x * 8;
    if (t == 0) {
        for (int i = tid; i < 512; i += 256) qsS[i] = 0.f;
        hhS[tid] = 0.f; ccS[tid] = 0.f;
    } else {
        int bl = tid >> 5, o = tid & 31;
        int g = (b0 + bl) * 32 + o;
        qsS[bl * 64 + o]      = g_q[g];
        qsS[bl * 64 + 32 + o] = g_rnum[g] / g_sumexp[b0 + bl];
        hhS[tid] = g_hh[g];
        ccS[tid] = g_cc[g];
    }
    __syncthreads();
    int bl = tid >> 5, o = tid & 31;
    int g = (b0 + bl) * 32 + o;
    g_rnum[g] = 0.f;
    if (tid < 8) g_sumexp[b0 + tid] = 0.f;
    float gi = b_ih[o]      + b_hh[o];
    float gf = b_ih[32 + o] + b_hh[32 + o];
    float gg = b_ih[64 + o] + b_hh[64 + o];
    float go = b_ih[96 + o] + b_hh[96 + o];
#pragma unroll 8
    for (int j = 0; j < 64; j++) {
        float q = qsS[bl * 64 + j];
        gi += q * w_ih[j * 128 + o];      gf += q * w_ih[j * 128 + 32 + o];
        gg += q * w_ih[j * 128 + 64 + o]; go += q * w_ih[j * 128 + 96 + o];
    }
#pragma unroll 8
    for (int j = 0; j < 32; j++) {
        float h = hhS[bl * 32 + j];
        gi += h * w_hh[j * 128 + o];      gf += h * w_hh[j * 128 + 32 + o];
        gg += h * w_hh[j * 128 + 64 + o]; go += h * w_hh[j * 128 + 96 + o];
    }
    float igt = 1.f / (1.f + expf(-gi));
    float fgt = 1.f / (1.f + expf(-gf));
    float ogt = 1.f / (1.f + expf(-go));
    float cnew = fgt * ccS[tid] + igt * tanhf(gg);
    float hnew = ogt * tanhf(cnew);
    g_cc[g] = cnew; g_hh[g] = hnew; g_q[g] = hnew;
}

// ---------------- attention pass ----------------
__global__ void k_att(const int* __restrict__ batch, int n_nodes) {
    int gw = (blockIdx.x * blockDim.x + threadIdx.x) >> 5;
    int lane = threadIdx.x & 31;
    if (gw >= n_nodes) return;
    int n = gw, b = batch[n];
    float ov = g_out[n * 32 + lane];
    float p = ov * g_q[b * 32 + lane];
#pragma unroll
    for (int s = 16; s; s >>= 1) p += __shfl_xor_sync(0xffffffffu, p, s);
    float ew = expf(p);
    atomicAdd(&g_rnum[b * 32 + lane], ew * ov);
    if (lane == 0) atomicAdd(&g_sumexp[b], ew);
}

// ---------------- final MLP ----------------
__global__ void k_final(const float* __restrict__ lin1_w, const float* __restrict__ lin1_b,
                        const float* __restrict__ lin2_w, const float* __restrict__ lin2_b,
                        float* __restrict__ out) {
    int b = blockIdx.x, c = threadIdx.x;  // 64 x 32
    float y = lin1_b[c];
#pragma unroll 8
    for (int j = 0; j < 32; j++) y += g_q[b * 32 + j] * lin1_w[j * 32 + c];
    float inv = 1.f / g_sumexp[b];
#pragma unroll 8
    for (int j = 0; j < 32; j++) y += (g_rnum[b * 32 + j] * inv) * lin1_w[(32 + j) * 32 + c];
    y = fmaxf(y, 0.f);
    float p = y * lin2_w[c];
#pragma unroll
    for (int s = 16; s; s >>= 1) p += __shfl_xor_sync(0xffffffffu, p, s);
    if (c == 0) out[b] = p + lin2_b[0];
}

// ---------------- launcher (single stream) ----------------
extern "C" void kernel_launch(void* const* d_in, const int* in_sizes, int n_in,
                              void* d_out, int out_size) {
    const float* x         = (const float*)d_in[0];
    const float* edge_attr = (const float*)d_in[1];
    const float* lin0_w    = (const float*)d_in[2];
    const float* lin0_b    = (const float*)d_in[3];
    const float* nn_w1     = (const float*)d_in[4];
    const float* nn_b1     = (const float*)d_in[5];
    const float* nn_w2     = (const float*)d_in[6];
    const float* nn_b2     = (const float*)d_in[7];
    const float* conv_root = (const float*)d_in[8];
    const float* conv_bias = (const float*)d_in[9];
    const float* gru_w_ih  = (const float*)d_in[10];
    const float* gru_w_hh  = (const float*)d_in[11];
    const float* gru_b_ih  = (const float*)d_in[12];
    const float* gru_b_hh  = (const float*)d_in[13];
    const float* lstm_w_ih = (const float*)d_in[14];
    const float* lstm_w_hh = (const float*)d_in[15];
    const float* lstm_b_ih = (const float*)d_in[16];
    const float* lstm_b_hh = (const float*)d_in[17];
    const float* lin1_w    = (const float*)d_in[18];
    const float* lin1_b    = (const float*)d_in[19];
    const float* lin2_w    = (const float*)d_in[20];
    const float* lin2_b    = (const float*)d_in[21];
    const int*   ei        = (const int*)d_in[22];
    const int*   batch     = (const int*)d_in[23];

    int N = in_sizes[0];
    int E = in_sizes[1] / 2;
    int nh = (N + 1) / 2;

    // k_setup grid covers max(N*32, 32*4128) elements — N*32 here
    int setup_elems = N * 32 > 32 * 4128 ? N * 32 : 32 * 4128;
    k_setup<<<(setup_elems + 255) / 256, 256>>>(x, lin0_w, lin0_b, nn_w2, nn_b2, N);  // 1
    k_count<<<(E + 255) / 256, 256>>>(ei, E);                                         // 2
    k_scan<<<1, 1024>>>(N);                                                           // 3
    dim3 gA(9, (nh + 15) / 16);
    k_T<<<gA, 256>>>(0, nh);                                                          // 4 <- profiled
    k_scatter<<<(E + 255) / 256, 256>>>(ei, E);                                       // 5

    dim3 gB(9, (N - nh + 15) / 16);
    for (int it = 0; it < 3; it++) {
        if (it > 0) k_T<<<gA, 256>>>(0, nh);
        k_edge<<<nh, 128>>>(ei, edge_attr, nn_w1, nn_b1, E, 0);
        k_T<<<gB, 256>>>(nh, N);
        k_edge<<<N - nh, 128>>>(ei, edge_attr, nn_w1, nn_b1, E, nh);
        k_update<<<(N * 32 + 127) / 128, 128>>>(conv_root, conv_bias, gru_w_ih, gru_w_hh,
                                                gru_b_ih, gru_b_hh, N);
    }

    for (int t = 0; t < 3; t++) {
        k_lstm<<<8, 256>>>(lstm_w_ih, lstm_w_hh, lstm_b_ih, lstm_b_hh, t);
        k_att<<<(N * 32 + 255) / 256, 256>>>(batch, N);
    }
    k_final<<<64, 32>>>(lin1_w, lin1_b, lin2_w, lin2_b, (float*)d_out);
}

// round 15
// speedup vs baseline: 1.1218x; 1.1218x over previous
#include <cuda_runtime.h>
#include <math.h>

#define MAXN 10000
#define MAXE 160000
#define NB   64

typedef unsigned long long ull;
#define FMA2(d,a,b,c) asm("fma.rn.f32x2 %0, %1, %2, %3;" : "=l"(d) : "l"(a), "l"(b), "l"(c))
#define PACK2(d,x,y)  asm("mov.b64 %0, {%1, %2};" : "=l"(d) : "f"(x), "f"(y))

// ---------------- device scratch ----------------
__device__ float g_out[MAXN * 32];
__device__ float g_agg[MAXN * 32];
__device__ float g_deg[MAXN];
__device__ float g_W2x[32 * 4128];
__device__ float g_T  [MAXN * 4128];
__device__ int   g_cnt[MAXN];
__device__ int   g_off[MAXN];
__device__ int   g_pos[MAXN];
__device__ int   g_eid[MAXE];

// ---------------- fused setup: init out/agg/deg/cnt + W2x transform ----------------
// grid MUST cover max(N*32, 32*4128) indices
__global__ void k_setup(const float* __restrict__ x, const float* __restrict__ w0,
                        const float* __restrict__ b0,
                        const float* __restrict__ w2, const float* __restrict__ b2,
                        int n_nodes) {
    int idx = blockIdx.x * blockDim.x + threadIdx.x;
    if (idx < n_nodes) { g_deg[idx] = 0.f; g_cnt[idx] = 0; }
    if (idx < n_nodes * 32) {
        int n = idx >> 5, o = idx & 31;
        float v = x[n] * w0[o] + b0[o];
        g_out[idx] = v > 0.f ? v : 0.f;
        g_agg[idx] = 0.f;
    }
    if (idx < 32 * 4128) {
        int i = idx / 4128, c = idx % 4128;
        float v;
        if (c < 4096) { int k = c >> 5, o = c & 31; v = w2[k * 1024 + i * 32 + o]; }
        else          { v = b2[i * 32 + (c - 4096)]; }
        g_W2x[idx] = v;
    }
}

__global__ void k_count(const int* __restrict__ ei, int n_edges) {
    int e = blockIdx.x * blockDim.x + threadIdx.x;
    if (e >= n_edges) return;
    atomicAdd(&g_deg[ei[n_edges + e]], 1.0f);
    atomicAdd(&g_cnt[ei[e]], 1);
}

__global__ void k_scan(int n_nodes) {
    __shared__ int wsum[32];
    int tid = threadIdx.x;  // 1024
    int lane = tid & 31, wid = tid >> 5;
    int CH = (n_nodes + 1023) >> 10;
    int base = tid * CH;
    int s = 0;
#pragma unroll 4
    for (int j = 0; j < CH; j++) { int i = base + j; if (i < n_nodes) s += g_cnt[i]; }
    int v = s;
#pragma unroll
    for (int off = 1; off < 32; off <<= 1) {
        int u = __shfl_up_sync(0xffffffffu, v, off);
        if (lane >= off) v += u;
    }
    if (lane == 31) wsum[wid] = v;
    __syncthreads();
    if (wid == 0) {
        int w = wsum[lane];
#pragma unroll
        for (int off = 1; off < 32; off <<= 1) {
            int u = __shfl_up_sync(0xffffffffu, w, off);
            if (lane >= off) w += u;
        }
        wsum[lane] = w;
    }
    __syncthreads();
    int run = v - s + (wid ? wsum[wid - 1] : 0);
    for (int j = 0; j < CH; j++) {
        int i = base + j;
        if (i < n_nodes) { g_off[i] = run; g_pos[i] = run; run += g_cnt[i]; }
    }
}

__global__ void k_scatter(const int* __restrict__ ei, int n_edges) {
    int e = blockIdx.x * blockDim.x + threadIdx.x;
    if (e >= n_edges) return;
    int p = atomicAdd(&g_pos[ei[e]], 1);
    g_eid[p] = e;
}

// ---------------- T' = out @ W2x : 2 cols x 16 nodes, depth-2 W2x prefetch ----------------
__global__ void __launch_bounds__(256, 4) k_T(int n0, int n1) {
    __shared__ float outT[32 * 20];
    int ct = blockIdx.x;              // 0..8, 512-col tiles
    int tid = threadIdx.x;            // 256
    int nb = n0 + blockIdx.y * 16;
    for (int idx = tid; idx < 512; idx += 256) {
        int node = idx >> 5, i = idx & 31;
        int n = nb + node;
        outT[i * 20 + node] = (n < n1) ? g_out[n * 32 + i] : 0.f;
    }
    __syncthreads();
    int colA = ct * 512 + tid;
    int colB = colA + 256;
    bool vA = colA < 4128, vB = colB < 4128;
    if (!vA) return;
    const float* wAp = &g_W2x[colA];
    const float* wBp = &g_W2x[colB];
    ull accA[8], accB[8];
#pragma unroll
    for (int j = 0; j < 8; j++) { accA[j] = 0ull; accB[j] = 0ull; }
    float wa0 = wAp[0];
    float wb0 = vB ? wBp[0] : 0.f;
    float wa1 = wAp[4128];
    float wb1 = vB ? wBp[4128] : 0.f;
#pragma unroll
    for (int i = 0; i < 32; i++) {
        ull wpa, wpb;
        PACK2(wpa, wa0, wa0);
        PACK2(wpb, wb0, wb0);
        wa0 = wa1; wb0 = wb1;
        if (i < 30) {
            wa1 = wAp[(i + 2) * 4128];
            wb1 = vB ? wBp[(i + 2) * 4128] : 0.f;
        }
        const longlong2* op = (const longlong2*)&outT[i * 20];
#pragma unroll
        for (int q = 0; q < 4; q++) {
            longlong2 v = op[q];
            FMA2(accA[2 * q + 0], (ull)v.x, wpa, accA[2 * q + 0]);
            FMA2(accA[2 * q + 1], (ull)v.y, wpa, accA[2 * q + 1]);
            FMA2(accB[2 * q + 0], (ull)v.x, wpb, accB[2 * q + 0]);
            FMA2(accB[2 * q + 1], (ull)v.y, wpb, accB[2 * q + 1]);
        }
    }
#pragma unroll
    for (int j = 0; j < 8; j++) {
        float2 fA = *(float2*)&accA[j];
        float2 fB = *(float2*)&accB[j];
        int nA = nb + 2 * j;
        if (nA < n1) {
            g_T[(size_t)nA * 4128 + colA] = fA.x;
            if (vB) g_T[(size_t)nA * 4128 + colB] = fB.x;
        }
        if (nA + 1 < n1) {
            g_T[(size_t)(nA + 1) * 4128 + colA] = fA.y;
            if (vB) g_T[(size_t)(nA + 1) * 4128 + colB] = fB.y;
        }
    }
}

// ---------------- edge messages: 8-edge chunks, 2 warps/block (round-11 proven) ----------------
__global__ void k_edge(const int* __restrict__ ei, const float* __restrict__ ea,
                       const float* __restrict__ nn_w1, const float* __restrict__ nn_b1,
                       int n_edges, int n0) {
    __shared__ float Ts[4128];
    __shared__ float h1s[2][8 * 132];
    __shared__ int   eidS[2][8];
    __shared__ int   dstS[2][8];
    __shared__ float eaS[2][8][2];
    int n = n0 + blockIdx.x;
    int cnt = g_cnt[n];
    if (cnt == 0) return;
    int start = g_off[n];
    int tid = threadIdx.x;  // 64
    int w = tid >> 5, lane = tid & 31;
    float4 w1a = *(const float4*)&nn_w1[lane * 4];
    float4 w1b = *(const float4*)&nn_w1[128 + lane * 4];
    float4 b1v = *(const float4*)&nn_b1[lane * 4];
    {
        const float4* Tg = (const float4*)&g_T[(size_t)n * 4128];
        float4* Ts4 = (float4*)Ts;
        for (int i = tid; i < 1032; i += 64) Ts4[i] = Tg[i];
    }
    __syncthreads();
    int og = lane & 7;       // output group (4 floats)
    int eg = lane >> 3;      // edge pair 0..3 -> edges eg*2, eg*2+1
    const float* h0p = &h1s[w][(eg * 2 + 0) * 132];
    const float* h1p = &h1s[w][(eg * 2 + 1) * 132];
    int nch = (cnt + 7) >> 3;
    for (int c = w; c < nch; c += 2) {
        if (lane < 8) {
            int idx = c * 8 + lane;
            int e = (idx < cnt) ? g_eid[start + idx] : -1;
            eidS[w][lane] = e;
            dstS[w][lane] = (e >= 0) ? ei[n_edges + e] : 0;
            float2 e2 = (e >= 0) ? *(const float2*)&ea[2 * e] : make_float2(0.f, 0.f);
            eaS[w][lane][0] = e2.x; eaS[w][lane][1] = e2.y;
        }
        __syncwarp();
#pragma unroll
        for (int r = 0; r < 8; r++) {
            float a0 = eaS[w][r][0], a1 = eaS[w][r][1];
            float4 h;
            h.x = fmaxf(a0 * w1a.x + a1 * w1b.x + b1v.x, 0.f);
            h.y = fmaxf(a0 * w1a.y + a1 * w1b.y + b1v.y, 0.f);
            h.z = fmaxf(a0 * w1a.z + a1 * w1b.z + b1v.z, 0.f);
            h.w = fmaxf(a0 * w1a.w + a1 * w1b.w + b1v.w, 0.f);
            *(float4*)&h1s[w][r * 132 + lane * 4] = h;
        }
        __syncwarp();
        longlong2 bb = *(const longlong2*)&Ts[4096 + og * 4];
        ull a00 = (ull)bb.x, a01 = (ull)bb.y;
        ull a10 = (ull)bb.x, a11 = (ull)bb.y;
#pragma unroll 4
        for (int k = 0; k < 128; k += 4) {
            longlong2 t0 = *(const longlong2*)&Ts[(k + 0) * 32 + og * 4];
            longlong2 t1 = *(const longlong2*)&Ts[(k + 1) * 32 + og * 4];
            longlong2 t2 = *(const longlong2*)&Ts[(k + 2) * 32 + og * 4];
            longlong2 t3 = *(const longlong2*)&Ts[(k + 3) * 32 + og * 4];
            float4 h0 = *(const float4*)&h0p[k];
            float4 h1v = *(const float4*)&h1p[k];
            ull hh;
            PACK2(hh, h0.x, h0.x);
            FMA2(a00, hh, (ull)t0.x, a00); FMA2(a01, hh, (ull)t0.y, a01);
            PACK2(hh, h1v.x, h1v.x);
            FMA2(a10, hh, (ull)t0.x, a10); FMA2(a11, hh, (ull)t0.y, a11);
            PACK2(hh, h0.y, h0.y);
            FMA2(a00, hh, (ull)t1.x, a00); FMA2(a01, hh, (ull)t1.y, a01);
            PACK2(hh, h1v.y, h1v.y);
            FMA2(a10, hh, (ull)t1.x, a10); FMA2(a11, hh, (ull)t1.y, a11);
            PACK2(hh, h0.z, h0.z);
            FMA2(a00, hh, (ull)t2.x, a00); FMA2(a01, hh, (ull)t2.y, a01);
            PACK2(hh, h1v.z, h1v.z);
            FMA2(a10, hh, (ull)t2.x, a10); FMA2(a11, hh, (ull)t2.y, a11);
            PACK2(hh, h0.w, h0.w);
            FMA2(a00, hh, (ull)t3.x, a00); FMA2(a01, hh, (ull)t3.y, a01);
            PACK2(hh, h1v.w, h1v.w);
            FMA2(a10, hh, (ull)t3.x, a10); FMA2(a11, hh, (ull)t3.y, a11);
        }
        int e0 = eidS[w][eg * 2], e1 = eidS[w][eg * 2 + 1];
        if (e0 >= 0) {
            float2 f0 = *(float2*)&a00, f1 = *(float2*)&a01;
            float* ap = &g_agg[(size_t)dstS[w][eg * 2] * 32 + og * 4];
            atomicAdd(ap + 0, f0.x); atomicAdd(ap + 1, f0.y);
            atomicAdd(ap + 2, f1.x); atomicAdd(ap + 3, f1.y);
        }
        if (e1 >= 0) {
            float2 f0 = *(float2*)&a10, f1 = *(float2*)&a11;
            float* ap = &g_agg[(size_t)dstS[w][eg * 2 + 1] * 32 + og * 4];
            atomicAdd(ap + 0, f0.x); atomicAdd(ap + 1, f0.y);
            atomicAdd(ap + 2, f1.x); atomicAdd(ap + 3, f1.y);
        }
        __syncwarp();
    }
}

// ---------------- GRU node update (re-zeroes agg) ----------------
__global__ void k_update(const float* __restrict__ conv_root, const float* __restrict__ conv_bias,
                         const float* __restrict__ w_ih, const float* __restrict__ w_hh,
                         const float* __restrict__ b_ih, const float* __restrict__ b_hh,
                         int n_nodes) {
    int warp = (blockIdx.x * blockDim.x + threadIdx.x) >> 5;
    int lane = threadIdx.x & 31;
    if (warp >= n_nodes) return;
    int n = warp;
    float hv = g_out[n * 32 + lane];
    float m = g_agg[n * 32 + lane] / fmaxf(g_deg[n], 1.f) + conv_bias[lane];
    g_agg[n * 32 + lane] = 0.f;
#pragma unroll
    for (int i = 0; i < 32; i++) {
        float oi = __shfl_sync(0xffffffffu, hv, i);
        m += oi * conv_root[i * 32 + lane];
    }
    m = fmaxf(m, 0.f);
    float gr = b_ih[lane], gz = b_ih[32 + lane], gn = b_ih[64 + lane];
    float hr = b_hh[lane], hz = b_hh[32 + lane], hn = b_hh[64 + lane];
#pragma unroll
    for (int i = 0; i < 32; i++) {
        float mi = __shfl_sync(0xffffffffu, m, i);
        float hi = __shfl_sync(0xffffffffu, hv, i);
        gr += mi * w_ih[i * 96 + lane];
        gz += mi * w_ih[i * 96 + 32 + lane];
        gn += mi * w_ih[i * 96 + 64 + lane];
        hr += hi * w_hh[i * 96 + lane];
        hz += hi * w_hh[i * 96 + 32 + lane];
        hn += hi * w_hh[i * 96 + 64 + lane];
    }
    float rg = 1.f / (1.f + expf(-(gr + hr)));
    float zg = 1.f / (1.f + expf(-(gz + hz)));
    float ng = tanhf(gn + rg * hn);
    g_out[n * 32 + lane] = (1.f - zg) * ng + zg * hv;
}

// ---------------- fused Set2Set + final MLP: one block per graph ----------------
__global__ void k_s2s(const int* __restrict__ batch,
                      const float* __restrict__ w_ih, const float* __restrict__ w_hh,
                      const float* __restrict__ b_ih, const float* __restrict__ b_hh,
                      const float* __restrict__ lin1_w, const float* __restrict__ lin1_b,
                      const float* __restrict__ lin2_w, const float* __restrict__ lin2_b,
                      float* __restrict__ out, int n_nodes) {
    __shared__ float qstar[64];
    __shared__ float hhS[32], ccS[32];
    __shared__ float gates[128];
    __shared__ float wr[4][32];
    __shared__ float ws[4];
    int b = blockIdx.x;       // 64 graphs
    int tid = threadIdx.x;    // 128
    int w = tid >> 5, lane = tid & 31;
    // node range [lo,hi) for this graph (batch is sorted)
    int lo, hi;
    {
        int l = 0, r = n_nodes;
        while (l < r) { int m = (l + r) >> 1; if (batch[m] < b) l = m + 1; else r = m; }
        lo = l;
        r = n_nodes;
        while (l < r) { int m = (l + r) >> 1; if (batch[m] < b + 1) l = m + 1; else r = m; }
        hi = l;
    }
    if (tid < 64) qstar[tid] = 0.f;
    if (tid < 32) { hhS[tid] = 0.f; ccS[tid] = 0.f; }
    __syncthreads();
    for (int t = 0; t < 3; t++) {
        // LSTM gates: thread tid computes gate column tid (0..127)
        float g = b_ih[tid] + b_hh[tid];
#pragma unroll 8
        for (int j = 0; j < 64; j++) g += qstar[j] * w_ih[j * 128 + tid];
#pragma unroll 8
        for (int j = 0; j < 32; j++) g += hhS[j] * w_hh[j * 128 + tid];
        gates[tid] = g;
        __syncthreads();
        if (tid < 32) {
            float ig = 1.f / (1.f + expf(-gates[tid]));
            float fg = 1.f / (1.f + expf(-gates[32 + tid]));
            float gg = tanhf(gates[64 + tid]);
            float og = 1.f / (1.f + expf(-gates[96 + tid]));
            float c2 = fg * ccS[tid] + ig * gg;
            ccS[tid] = c2;
            hhS[tid] = og * tanhf(c2);
        }
        __syncthreads();
        // attention over this graph's nodes (warp per node, 4 warps round-robin)
        float q = hhS[lane];
        float lr = 0.f, lse = 0.f;
        for (int n = lo + w; n < hi; n += 4) {
            float ov = g_out[n * 32 + lane];
            float p = ov * q;
#pragma unroll
            for (int s = 16; s; s >>= 1) p += __shfl_xor_sync(0xffffffffu, p, s);
            float ew = expf(p);
            lr += ew * ov;
            lse += ew;        // identical across lanes
        }
        wr[w][lane] = lr;
        if (lane == 0) ws[w] = lse;
        __syncthreads();
        if (tid < 32) {
            float se = ws[0] + ws[1] + ws[2] + ws[3];
            float rv = wr[0][tid] + wr[1][tid] + wr[2][tid] + wr[3][tid];
            qstar[tid] = hhS[tid];
            qstar[32 + tid] = (se > 0.f) ? rv / se : 0.f;
        }
        __syncthreads();
    }
    // final MLP (warp 0): y = relu(q_star@lin1+b1) @ lin2 + b2
    if (w == 0) {
        float y = lin1_b[lane];
#pragma unroll 8
        for (int j = 0; j < 64; j++) y += qstar[j] * lin1_w[j * 32 + lane];
        y = fmaxf(y, 0.f);
        float p = y * lin2_w[lane];
#pragma unroll
        for (int s = 16; s; s >>= 1) p += __shfl_xor_sync(0xffffffffu, p, s);
        if (lane == 0) out[b] = p + lin2_b[0];
    }
}

// ---------------- launcher (single stream) ----------------
extern "C" void kernel_launch(void* const* d_in, const int* in_sizes, int n_in,
                              void* d_out, int out_size) {
    const float* x         = (const float*)d_in[0];
    const float* edge_attr = (const float*)d_in[1];
    const float* lin0_w    = (const float*)d_in[2];
    const float* lin0_b    = (const float*)d_in[3];
    const float* nn_w1     = (const float*)d_in[4];
    const float* nn_b1     = (const float*)d_in[5];
    const float* nn_w2     = (const float*)d_in[6];
    const float* nn_b2     = (const float*)d_in[7];
    const float* conv_root = (const float*)d_in[8];
    const float* conv_bias = (const float*)d_in[9];
    const float* gru_w_ih  = (const float*)d_in[10];
    const float* gru_w_hh  = (const float*)d_in[11];
    const float* gru_b_ih  = (const float*)d_in[12];
    const float* gru_b_hh  = (const float*)d_in[13];
    const float* lstm_w_ih = (const float*)d_in[14];
    const float* lstm_w_hh = (const float*)d_in[15];
    const float* lstm_b_ih = (const float*)d_in[16];
    const float* lstm_b_hh = (const float*)d_in[17];
    const float* lin1_w    = (const float*)d_in[18];
    const float* lin1_b    = (const float*)d_in[19];
    const float* lin2_w    = (const float*)d_in[20];
    const float* lin2_b    = (const float*)d_in[21];
    const int*   ei        = (const int*)d_in[22];
    const int*   batch     = (const int*)d_in[23];

    int N = in_sizes[0];
    int E = in_sizes[1] / 2;
    int nh = (N + 1) / 2;

    // k_setup grid covers max(N*32, 32*4128) elements
    int setup_elems = N * 32 > 32 * 4128 ? N * 32 : 32 * 4128;
    k_setup<<<(setup_elems + 255) / 256, 256>>>(x, lin0_w, lin0_b, nn_w2, nn_b2, N);  // 1
    k_count<<<(E + 255) / 256, 256>>>(ei, E);                                         // 2
    k_scan<<<1, 1024>>>(N);                                                           // 3
    dim3 gA(9, (nh + 15) / 16);
    k_T<<<gA, 256>>>(0, nh);                                                          // 4 <- profiled
    k_scatter<<<(E + 255) / 256, 256>>>(ei, E);                                       // 5

    dim3 gB(9, (N - nh + 15) / 16);
    for (int it = 0; it < 3; it++) {
        if (it > 0) k_T<<<gA, 256>>>(0, nh);
        k_edge<<<nh, 64>>>(ei, edge_attr, nn_w1, nn_b1, E, 0);
        k_T<<<gB, 256>>>(nh, N);
        k_edge<<<N - nh, 64>>>(ei, edge_attr, nn_w1, nn_b1, E, nh);
        k_update<<<(N * 32 + 127) / 128, 128>>>(conv_root, conv_bias, gru_w_ih, gru_w_hh,
                                                gru_b_ih, gru_b_hh, N);
    }

    k_s2s<<<64, 128>>>(batch, lstm_w_ih, lstm_w_hh, lstm_b_ih, lstm_b_hh,
                       lin1_w, lin1_b, lin2_w, lin2_b, (float*)d_out, N);
}